// round 16
// baseline (speedup 1.0000x reference)
#include <cuda_runtime.h>
#include <cstdint>

#define BB 4
#define SS 2048
#define HH 1024
#define HDD 64
#define BH 64

// Scratch, all tf32-rounded by producers:
// Q [B*NH][S][HD], hd pos16-permuted, pre-scaled 0.125*log2(e)
// K [B*NH][S][HD], hd pos16-permuted AND s(key) perm8-permuted within 8
// V transposed [B*NH][HD][S], key-dim pos16-permuted, PRE-SCALED by exp2(mask*log2e)
__device__ float g_q[BB*SS*HH];
__device__ float g_k[BB*SS*HH];
__device__ float g_v[BB*SS*HH];
// Pre-rounded, pos16-permuted GEMM inputs
__device__ float g_xr[BB*SS*HH];
__device__ float g_wq[HH*HH];
__device__ float g_wk[HH*HH];
__device__ float g_wv[HH*HH];

#define LOG2E 1.44269504f

__device__ __forceinline__ float tf32r(float x) {
    uint32_t r;
    asm("cvt.rna.tf32.f32 %0, %1;" : "=r"(r) : "f"(x));
    return __uint_as_float(r);
}
__device__ __forceinline__ uint32_t fb(float x) { return __float_as_uint(x); }
__device__ __forceinline__ int perm8(int c) { return ((c & 3) << 1) | ((c >> 2) & 1); }
// 16-group interleave: position of original index j (two 8-groups fused)
__device__ __forceinline__ int pos16(int j) {
    return ((j & 3) << 2) | (((j >> 3) & 1) << 1) | ((j >> 2) & 1);
}

__device__ __forceinline__ void mma8(float c[4],
                                     uint32_t a0, uint32_t a1, uint32_t a2, uint32_t a3,
                                     uint32_t b0, uint32_t b1) {
    asm volatile(
        "mma.sync.aligned.m16n8k8.row.col.f32.tf32.tf32.f32 "
        "{%0,%1,%2,%3},{%4,%5,%6,%7},{%8,%9},{%0,%1,%2,%3};\n"
        : "+f"(c[0]), "+f"(c[1]), "+f"(c[2]), "+f"(c[3])
        : "r"(a0), "r"(a1), "r"(a2), "r"(a3), "r"(b0), "r"(b1));
}

__device__ __forceinline__ void cpasync16(uint32_t dst_smem, const void* src) {
    asm volatile("cp.async.cg.shared.global [%0], [%1], 16;\n"
                 :: "r"(dst_smem), "l"(src));
}
__device__ __forceinline__ void cpcommit() { asm volatile("cp.async.commit_group;\n"); }
__device__ __forceinline__ void cpwait0()  { asm volatile("cp.async.wait_group 0;\n"); }

// ======================= Pre-round + pos16-permute X and W =======================
#define XGRP16 (BB*SS*HH/16)
#define WGRP16 (HH*HH/16)
__global__ __launch_bounds__(256) void preround_kernel(
    const float* __restrict__ X, const float* __restrict__ Wq,
    const float* __restrict__ Wk, const float* __restrict__ Wv)
{
    int gid = blockIdx.x * 256 + threadIdx.x;
    const float* src; float* dst; int off;
    if (gid < XGRP16) { src = X; dst = g_xr; off = gid * 16; }
    else {
        int w = gid - XGRP16;
        int which = w / WGRP16, rem = w % WGRP16;
        off = rem * 16;
        if (which == 0)      { src = Wq; dst = g_wq; }
        else if (which == 1) { src = Wk; dst = g_wk; }
        else                 { src = Wv; dst = g_wv; }
    }
    float4 r0 = *(const float4*)&src[off];
    float4 r1 = *(const float4*)&src[off + 4];
    float4 r2 = *(const float4*)&src[off + 8];
    float4 r3 = *(const float4*)&src[off + 12];
    *(float4*)&dst[off]      = make_float4(tf32r(r0.x), tf32r(r1.x), tf32r(r2.x), tf32r(r3.x));
    *(float4*)&dst[off + 4]  = make_float4(tf32r(r0.y), tf32r(r1.y), tf32r(r2.y), tf32r(r3.y));
    *(float4*)&dst[off + 8]  = make_float4(tf32r(r0.z), tf32r(r1.z), tf32r(r2.z), tf32r(r3.z));
    *(float4*)&dst[off + 12] = make_float4(tf32r(r0.w), tf32r(r1.w), tf32r(r2.w), tf32r(r3.w));
}

// ======================= QKV projection GEMM =======================
// CTA tile 256m x 128n @ 512 threads (16 warps, warp tile 64x32 unchanged),
// 1 CTA/SM (same 16 warps/SM, same reg budget as 2x256). B L2-traffic halves.
// pos16 -> one LDS.128 feeds TWO mmas; GSTR=48 conflict-free.
#define GSTR 48
#define GATILE (256 * GSTR)
#define GBTILE (128 * GSTR)
#define GEMM_SMEM ((2 * GATILE + 2 * GBTILE) * (int)sizeof(float))

__global__ __launch_bounds__(512, 1) void qkv_gemm_kernel(
    const float* __restrict__ bq, const float* __restrict__ bk,
    const float* __restrict__ bv, const float* __restrict__ mask)
{
    extern __shared__ float gs[];
    float* Abuf = gs;
    float* Bbuf = gs + 2 * GATILE;

    const float* W; const float* bias; float* out;
    if (blockIdx.z == 0)      { W = g_wq; bias = bq; out = g_q; }
    else if (blockIdx.z == 1) { W = g_wk; bias = bk; out = g_k; }
    else                      { W = g_wv; bias = bv; out = g_v; }
    const bool vtrans = (blockIdx.z == 2);
    const bool kperm  = (blockIdx.z == 1);
    const float oscale = (blockIdx.z == 0) ? (0.125f * LOG2E) : 1.0f;

    const int m0 = blockIdx.x * 256;
    const int n0 = blockIdx.y * 128;
    const int tid = threadIdx.x;
    const int lane = tid & 31, warp = tid >> 5;
    const int wm = warp >> 2, wn = warp & 3;      // 4 x 4 warps, 64x32 tiles
    const int g = lane >> 2, tg = lane & 3;
    const uint32_t sbase = (uint32_t)__cvta_generic_to_shared(gs);
    const uint32_t bbase = sbase + 2 * GATILE * 4;
    const float* Xr = g_xr;

    float acc[4][4][4];
    #pragma unroll
    for (int mt = 0; mt < 4; mt++)
        #pragma unroll
        for (int nt = 0; nt < 4; nt++)
            #pragma unroll
            for (int j = 0; j < 4; j++) acc[mt][nt][j] = 0.f;

    {
        #pragma unroll
        for (int i = 0; i < 4; i++) {              // A: 2048 chunks
            int c = tid + i * 512;
            int row = c >> 3, c4 = (c & 7) * 4;
            cpasync16(sbase + (row * GSTR + c4) * 4,
                      &Xr[(size_t)(m0 + row) * HH + c4]);
        }
        #pragma unroll
        for (int i = 0; i < 2; i++) {              // B: 1024 chunks
            int c = tid + i * 512;
            int row = c >> 3, c4 = (c & 7) * 4;
            cpasync16(bbase + (row * GSTR + c4) * 4,
                      &W[(size_t)(n0 + row) * HH + c4]);
        }
        cpcommit();
    }

    for (int t = 0; t < 32; t++) {
        const int cur = t & 1;
        cpwait0();
        __syncthreads();

        if (t + 1 < 32) {
            const int nxt = cur ^ 1;
            const int k0 = (t + 1) * 32;
            #pragma unroll
            for (int i = 0; i < 4; i++) {
                int c = tid + i * 512;
                int row = c >> 3, c4 = (c & 7) * 4;
                cpasync16(sbase + (nxt * GATILE + row * GSTR + c4) * 4,
                          &Xr[(size_t)(m0 + row) * HH + k0 + c4]);
            }
            #pragma unroll
            for (int i = 0; i < 2; i++) {
                int c = tid + i * 512;
                int row = c >> 3, c4 = (c & 7) * 4;
                cpasync16(bbase + (nxt * GBTILE + row * GSTR + c4) * 4,
                          &W[(size_t)(n0 + row) * HH + k0 + c4]);
            }
            cpcommit();
        }

        float* As = Abuf + cur * GATILE;
        float* Bs = Bbuf + cur * GBTILE;

        #pragma unroll
        for (int kp = 0; kp < 2; kp++) {      // each kp = two k8-groups
            float4 aA[4], aB[4];
            #pragma unroll
            for (int mt = 0; mt < 4; mt++) {
                int r = wm * 64 + mt * 16 + g;
                aA[mt] = *(const float4*)&As[r * GSTR + kp * 16 + 4 * tg];
                aB[mt] = *(const float4*)&As[(r + 8) * GSTR + kp * 16 + 4 * tg];
            }
            #pragma unroll
            for (int nt = 0; nt < 4; nt++) {
                int n = wn * 32 + nt * 8 + g;
                float4 b4 = *(const float4*)&Bs[n * GSTR + kp * 16 + 4 * tg];
                #pragma unroll
                for (int mt = 0; mt < 4; mt++) {
                    mma8(acc[mt][nt], fb(aA[mt].x), fb(aB[mt].x),
                                      fb(aA[mt].y), fb(aB[mt].y),
                                      fb(b4.x), fb(b4.y));
                    mma8(acc[mt][nt], fb(aA[mt].z), fb(aB[mt].z),
                                      fb(aA[mt].w), fb(aB[mt].w),
                                      fb(b4.z), fb(b4.w));
                }
            }
        }
    }
    __syncthreads();

    // Epilogue: bias + tf32 round + scatter with pos16/perm8 permutations.
    #pragma unroll
    for (int mt = 0; mt < 4; mt++) {
        int r = m0 + wm * 64 + mt * 16 + g;
        int b_  = r >> 11, s_ = r & 2047;
        int b8_ = (r + 8) >> 11, s8_ = (r + 8) & 2047;
        float em0 = 1.f, em8 = 1.f;
        if (vtrans) {
            em0 = exp2f(mask[b_  * SS + s_ ] * LOG2E);
            em8 = exp2f(mask[b8_ * SS + s8_] * LOG2E);
        }
        #pragma unroll
        for (int nt = 0; nt < 4; nt++) {
            int c = n0 + wn * 32 + nt * 8 + 2 * tg;
            int nh = (c >> 6) & 15, hd = c & 63;
            float bi0 = bias[c], bi1 = bias[c + 1];
            int h0 = (b_  << 4) + nh;
            int h8 = (b8_ << 4) + nh;
            if (vtrans) {
                float v0 = tf32r((acc[mt][nt][0] + bi0) * em0);
                float v1 = tf32r((acc[mt][nt][1] + bi1) * em0);
                float v2 = tf32r((acc[mt][nt][2] + bi0) * em8);
                float v3 = tf32r((acc[mt][nt][3] + bi1) * em8);
                int sp0 = (s_  & ~15) | pos16(s_  & 15);
                int sp8 = (s8_ & ~15) | pos16(s8_ & 15);
                int t0 = (h0 * HDD + hd) * SS + sp0;
                int t8 = (h8 * HDD + hd) * SS + sp8;
                out[t0]      = v0;
                out[t0 + SS] = v1;
                out[t8]      = v2;
                out[t8 + SS] = v3;
            } else {
                float v0 = tf32r((acc[mt][nt][0] + bi0) * oscale);
                float v1 = tf32r((acc[mt][nt][1] + bi1) * oscale);
                float v2 = tf32r((acc[mt][nt][2] + bi0) * oscale);
                float v3 = tf32r((acc[mt][nt][3] + bi1) * oscale);
                int l = hd & 15;
                int p0 = (hd & ~15) | pos16(l);
                int p1 = (hd & ~15) | pos16(l + 1);
                int so_ = s_, so8 = s8_;
                if (kperm) {
                    so_ = (s_  & ~7) | perm8(s_  & 7);
                    so8 = (s8_ & ~7) | perm8(s8_ & 7);
                }
                int base0 = (h0 * SS + so_) * HDD;
                int base8 = (h8 * SS + so8) * HDD;
                out[base0 + p0] = v0;
                out[base0 + p1] = v1;
                out[base8 + p0] = v2;
                out[base8 + p1] = v3;
            }
        }
    }
}

// ======================= Flash attention (R15, unchanged) =======================
// 8 warps, 128 q-rows, 2 CTA/SM. Mask folded into V -> p = exp2(s) directly.
// l computed by the tensor core as a 9th PV n-group (row 64 = em[key]).
#define KSTR 80
#define TILE_K (64 * KSTR)
#define TILE_V (72 * KSTR)
#define ATTN_SMEM ((2 * TILE_K + 2 * TILE_V + SS) * (int)sizeof(float))

__global__ __launch_bounds__(256, 2) void attn_kernel(const float* __restrict__ mask,
                                                      float* __restrict__ out)
{
    extern __shared__ float sm[];
    float* Kst = sm;                       // 2 stages [64][KSTR]
    float* Vst = sm + 2 * TILE_K;          // 2 stages [72][KSTR] (row 64 = em)
    float* Em  = sm + 2 * TILE_K + 2 * TILE_V;  // em_all[2048], pos16-permuted

    const int tid = threadIdx.x;
    const int lane = tid & 31, warp = tid >> 5;
    const int g = lane >> 2, tg = lane & 3;
    const int hbh = blockIdx.y;
    const int b = hbh >> 4, nh = hbh & 15;
    const int q0 = blockIdx.x * 128;
    const int r0 = warp * 16;

    const float* qb  = g_q + ((size_t)hbh * SS + q0) * HDD;
    const float* kb  = g_k + (size_t)hbh * SS * HDD;
    const float* vtb = g_v + (size_t)hbh * HDD * SS;
    const float* mrow = mask + b * SS;

    // em_all (pos16-permuted to match V key layout) + zero Vt rows 64..71
    #pragma unroll
    for (int i = 0; i < 8; i++) {
        int idx = tid + i * 256;
        Em[(idx & ~15) | pos16(idx & 15)] = exp2f(mrow[idx] * LOG2E);
    }
    for (int i = tid; i < 2 * 8 * KSTR; i += 256) {
        int stage = i / (8 * KSTR), rem = i % (8 * KSTR);
        Vst[stage * TILE_V + (64 + rem / KSTR) * KSTR + (rem % KSTR)] = 0.f;
    }
    if (tid < 64)
        Vst[64 * KSTR + ((tid & ~15) | pos16(tid & 15))] = exp2f(mrow[tid] * LOG2E);

    // Q fragments: hd pos16'd -> one LDG.128 covers both k8-groups of a pair
    uint32_t qa[4][8];
    #pragma unroll
    for (int kp = 0; kp < 4; kp++) {
        float4 qA = *(const float4*)&qb[(r0 + g)     * 64 + kp * 16 + 4 * tg];
        float4 qB = *(const float4*)&qb[(r0 + 8 + g) * 64 + kp * 16 + 4 * tg];
        qa[kp][0] = fb(qA.x); qa[kp][1] = fb(qB.x);
        qa[kp][2] = fb(qA.y); qa[kp][3] = fb(qB.y);
        qa[kp][4] = fb(qA.z); qa[kp][5] = fb(qB.z);
        qa[kp][6] = fb(qA.w); qa[kp][7] = fb(qB.w);
    }

    const uint32_t smem_base = (uint32_t)__cvta_generic_to_shared(sm);
    const uint32_t vbase = smem_base + 2 * TILE_K * 4;

    float O[9][4];
    #pragma unroll
    for (int nt = 0; nt < 9; nt++)
        #pragma unroll
        for (int j = 0; j < 4; j++) O[nt][j] = 0.f;

    {
        #pragma unroll
        for (int i = 0; i < 4; i++) {
            int c = tid + i * 256;
            int row = c >> 4, c4 = (c & 15) * 4;
            cpasync16(smem_base + (row * KSTR + c4) * 4, &kb[row * 64 + c4]);
            cpasync16(vbase + (row * KSTR + c4) * 4, &vtb[(size_t)row * SS + c4]);
        }
        cpcommit();
    }

    for (int kt = 0; kt < 32; kt++) {
        const int cur = kt & 1;
        float* Ks = Kst + cur * TILE_K;
        float* Vt = Vst + cur * TILE_V;

        cpwait0();
        __syncthreads();

        if (kt + 1 < 32) {
            const int nxt = (kt + 1) & 1;
            const int koff = (kt + 1) * 64;
            #pragma unroll
            for (int i = 0; i < 4; i++) {
                int c = tid + i * 256;
                int row = c >> 4, c4 = (c & 15) * 4;
                cpasync16(smem_base + (nxt * TILE_K + row * KSTR + c4) * 4,
                          &kb[(koff + row) * 64 + c4]);
                cpasync16(vbase + (nxt * TILE_V + row * KSTR + c4) * 4,
                          &vtb[(size_t)row * SS + koff + c4]);
            }
            cpcommit();
            if (tid < 64)
                Vst[nxt * TILE_V + 64 * KSTR + tid] = Em[koff + tid];
        }

        // S = Q K^T (log2 domain, mask-free)
        float s[8][4];
        #pragma unroll
        for (int kg = 0; kg < 8; kg++)
            #pragma unroll
            for (int j = 0; j < 4; j++) s[kg][j] = 0.f;

        #pragma unroll
        for (int kp = 0; kp < 4; kp++) {
            #pragma unroll
            for (int kg = 0; kg < 8; kg++) {
                float4 kk = *(const float4*)&Ks[(kg * 8 + g) * KSTR + kp * 16 + 4 * tg];
                mma8(s[kg], qa[kp][0], qa[kp][1], qa[kp][2], qa[kp][3],
                     fb(kk.x), fb(kk.y));
                mma8(s[kg], qa[kp][4], qa[kp][5], qa[kp][6], qa[kp][7],
                     fb(kk.z), fb(kk.w));
            }
        }

        // exp2 per element, then PV over 9 n-groups (group 8 = l column)
        #pragma unroll
        for (int kp = 0; kp < 4; kp++) {
            #pragma unroll
            for (int h = 0; h < 2; h++) {
                int kg = 2 * kp + h;
                s[kg][0] = exp2f(s[kg][0]);
                s[kg][1] = exp2f(s[kg][1]);
                s[kg][2] = exp2f(s[kg][2]);
                s[kg][3] = exp2f(s[kg][3]);
            }
            #pragma unroll
            for (int nt = 0; nt < 9; nt++) {
                float4 vv = *(const float4*)&Vt[(nt * 8 + g) * KSTR + kp * 16 + 4 * tg];
                mma8(O[nt], fb(s[2 * kp][0]), fb(s[2 * kp][2]),
                            fb(s[2 * kp][1]), fb(s[2 * kp][3]),
                     fb(vv.x), fb(vv.y));
                mma8(O[nt], fb(s[2 * kp + 1][0]), fb(s[2 * kp + 1][2]),
                            fb(s[2 * kp + 1][1]), fb(s[2 * kp + 1][3]),
                     fb(vv.z), fb(vv.w));
            }
        }
    }

    // l lives in O[8][0] (row g) / O[8][2] (row g+8) of the tg=0 lane
    float lsum0 = __shfl_sync(0xffffffffu, O[8][0], lane & ~3);
    float lsum1 = __shfl_sync(0xffffffffu, O[8][2], lane & ~3);
    float i0 = 1.f / lsum0, i1 = 1.f / lsum1;

    int rg  = q0 + r0 + g;
    int rg8 = rg + 8;
    #pragma unroll
    for (int nt = 0; nt < 8; nt++) {
        int hd = nt * 8 + 2 * tg;
        int o0 = (b * SS + rg ) * HH + nh * 64 + hd;
        int o8 = (b * SS + rg8) * HH + nh * 64 + hd;
        out[o0]     = O[nt][0] * i0;
        out[o0 + 1] = O[nt][1] * i0;
        out[o8]     = O[nt][2] * i1;
        out[o8 + 1] = O[nt][3] * i1;
    }
}

extern "C" void kernel_launch(void* const* d_in, const int* in_sizes, int n_in,
                              void* d_out, int out_size)
{
    const float* X    = (const float*)d_in[0];
    const float* mask = (const float*)d_in[1];
    const float* Wq   = (const float*)d_in[2];
    const float* bq   = (const float*)d_in[3];
    const float* Wk   = (const float*)d_in[4];
    const float* bk   = (const float*)d_in[5];
    const float* Wv   = (const float*)d_in[6];
    const float* bv   = (const float*)d_in[7];
    float* out = (float*)d_out;

    cudaFuncSetAttribute(qkv_gemm_kernel, cudaFuncAttributeMaxDynamicSharedMemorySize, GEMM_SMEM);
    cudaFuncSetAttribute(attn_kernel, cudaFuncAttributeMaxDynamicSharedMemorySize, ATTN_SMEM);

    int total_groups = XGRP16 + 3 * WGRP16;
    preround_kernel<<<total_groups / 256, 256>>>(X, Wq, Wk, Wv);

    dim3 gg(8192 / 256, HH / 128, 3);
    qkv_gemm_kernel<<<gg, 512, GEMM_SMEM>>>(bq, bk, bv, mask);

    dim3 ga(SS / 128, BH);
    attn_kernel<<<ga, 256, ATTN_SMEM>>>(mask, out);
}

// round 17
// speedup vs baseline: 1.1179x; 1.1179x over previous
#include <cuda_runtime.h>
#include <cstdint>

#define BB 4
#define SS 2048
#define HH 1024
#define HDD 64
#define BH 64

// Scratch, all tf32-rounded by producers:
// Q [B*NH][S][HD], hd pos16-permuted, pre-scaled 0.125*log2(e)
// K [B*NH][S][HD], hd pos16-permuted AND s(key) perm8-permuted within 8
// V transposed [B*NH][HD][S], key-dim pos16-permuted, PRE-SCALED by exp2(mask*log2e)
__device__ float g_q[BB*SS*HH];
__device__ float g_k[BB*SS*HH];
__device__ float g_v[BB*SS*HH];
// Pre-rounded, pos16-permuted GEMM inputs
__device__ float g_xr[BB*SS*HH];
__device__ float g_wq[HH*HH];
__device__ float g_wk[HH*HH];
__device__ float g_wv[HH*HH];

#define LOG2E 1.44269504f

__device__ __forceinline__ float tf32r(float x) {
    uint32_t r;
    asm("cvt.rna.tf32.f32 %0, %1;" : "=r"(r) : "f"(x));
    return __uint_as_float(r);
}
__device__ __forceinline__ uint32_t fb(float x) { return __float_as_uint(x); }
__device__ __forceinline__ int perm8(int c) { return ((c & 3) << 1) | ((c >> 2) & 1); }
// 16-group interleave: position of original index j (two 8-groups fused)
__device__ __forceinline__ int pos16(int j) {
    return ((j & 3) << 2) | (((j >> 3) & 1) << 1) | ((j >> 2) & 1);
}

__device__ __forceinline__ void mma8(float c[4],
                                     uint32_t a0, uint32_t a1, uint32_t a2, uint32_t a3,
                                     uint32_t b0, uint32_t b1) {
    asm volatile(
        "mma.sync.aligned.m16n8k8.row.col.f32.tf32.tf32.f32 "
        "{%0,%1,%2,%3},{%4,%5,%6,%7},{%8,%9},{%0,%1,%2,%3};\n"
        : "+f"(c[0]), "+f"(c[1]), "+f"(c[2]), "+f"(c[3])
        : "r"(a0), "r"(a1), "r"(a2), "r"(a3), "r"(b0), "r"(b1));
}

__device__ __forceinline__ void cpasync16(uint32_t dst_smem, const void* src) {
    asm volatile("cp.async.cg.shared.global [%0], [%1], 16;\n"
                 :: "r"(dst_smem), "l"(src));
}
__device__ __forceinline__ void cpcommit() { asm volatile("cp.async.commit_group;\n"); }
__device__ __forceinline__ void cpwait0()  { asm volatile("cp.async.wait_group 0;\n"); }

// ======================= Pre-round + pos16-permute X and W =======================
#define XGRP16 (BB*SS*HH/16)
#define WGRP16 (HH*HH/16)
__global__ __launch_bounds__(256) void preround_kernel(
    const float* __restrict__ X, const float* __restrict__ Wq,
    const float* __restrict__ Wk, const float* __restrict__ Wv)
{
    int gid = blockIdx.x * 256 + threadIdx.x;
    const float* src; float* dst; int off;
    if (gid < XGRP16) { src = X; dst = g_xr; off = gid * 16; }
    else {
        int w = gid - XGRP16;
        int which = w / WGRP16, rem = w % WGRP16;
        off = rem * 16;
        if (which == 0)      { src = Wq; dst = g_wq; }
        else if (which == 1) { src = Wk; dst = g_wk; }
        else                 { src = Wv; dst = g_wv; }
    }
    float4 r0 = *(const float4*)&src[off];
    float4 r1 = *(const float4*)&src[off + 4];
    float4 r2 = *(const float4*)&src[off + 8];
    float4 r3 = *(const float4*)&src[off + 12];
    *(float4*)&dst[off]      = make_float4(tf32r(r0.x), tf32r(r1.x), tf32r(r2.x), tf32r(r3.x));
    *(float4*)&dst[off + 4]  = make_float4(tf32r(r0.y), tf32r(r1.y), tf32r(r2.y), tf32r(r3.y));
    *(float4*)&dst[off + 8]  = make_float4(tf32r(r0.z), tf32r(r1.z), tf32r(r2.z), tf32r(r3.z));
    *(float4*)&dst[off + 12] = make_float4(tf32r(r0.w), tf32r(r1.w), tf32r(r2.w), tf32r(r3.w));
}

// ======================= QKV projection GEMM (R15 config, unchanged) ============
// 128x128 tile, 2-stage cp.async, pos16 -> one LDS.128 feeds TWO mmas.
// V epilogue folds exp2(mask*log2e) into V columns; Q folds 0.125*log2(e).
#define GSTR 48
#define GTILE (128 * GSTR)
#define GEMM_SMEM (4 * GTILE * (int)sizeof(float))

__global__ __launch_bounds__(256) void qkv_gemm_kernel(
    const float* __restrict__ bq, const float* __restrict__ bk,
    const float* __restrict__ bv, const float* __restrict__ mask)
{
    extern __shared__ float gs[];

    const float* W; const float* bias; float* out;
    if (blockIdx.z == 0)      { W = g_wq; bias = bq; out = g_q; }
    else if (blockIdx.z == 1) { W = g_wk; bias = bk; out = g_k; }
    else                      { W = g_wv; bias = bv; out = g_v; }
    const bool vtrans = (blockIdx.z == 2);
    const bool kperm  = (blockIdx.z == 1);
    const float oscale = (blockIdx.z == 0) ? (0.125f * LOG2E) : 1.0f;

    const int m0 = blockIdx.x * 128;
    const int n0 = blockIdx.y * 128;
    const int tid = threadIdx.x;
    const int lane = tid & 31, warp = tid >> 5;
    const int wm = warp >> 2, wn = warp & 3;
    const int g = lane >> 2, tg = lane & 3;
    const uint32_t sbase = (uint32_t)__cvta_generic_to_shared(gs);
    const float* Xr = g_xr;

    float acc[4][4][4];
    #pragma unroll
    for (int mt = 0; mt < 4; mt++)
        #pragma unroll
        for (int nt = 0; nt < 4; nt++)
            #pragma unroll
            for (int j = 0; j < 4; j++) acc[mt][nt][j] = 0.f;

    {
        #pragma unroll
        for (int i = 0; i < 4; i++) {
            int c = tid + i * 256;
            int row = c >> 3, c4 = (c & 7) * 4;
            cpasync16(sbase + (row * GSTR + c4) * 4,
                      &Xr[(size_t)(m0 + row) * HH + c4]);
            cpasync16(sbase + (2 * GTILE + row * GSTR + c4) * 4,
                      &W[(size_t)(n0 + row) * HH + c4]);
        }
        cpcommit();
    }

    for (int t = 0; t < 32; t++) {
        const int cur = t & 1;
        cpwait0();
        __syncthreads();

        if (t + 1 < 32) {
            const int nxt = cur ^ 1;
            const int k0 = (t + 1) * 32;
            #pragma unroll
            for (int i = 0; i < 4; i++) {
                int c = tid + i * 256;
                int row = c >> 3, c4 = (c & 7) * 4;
                cpasync16(sbase + (nxt * GTILE + row * GSTR + c4) * 4,
                          &Xr[(size_t)(m0 + row) * HH + k0 + c4]);
                cpasync16(sbase + ((2 + nxt) * GTILE + row * GSTR + c4) * 4,
                          &W[(size_t)(n0 + row) * HH + k0 + c4]);
            }
            cpcommit();
        }

        float* As = gs + cur * GTILE;
        float* Bs = gs + (2 + cur) * GTILE;

        #pragma unroll
        for (int kp = 0; kp < 2; kp++) {      // each kp = two k8-groups
            float4 aA[4], aB[4];
            #pragma unroll
            for (int mt = 0; mt < 4; mt++) {
                int r = wm * 64 + mt * 16 + g;
                aA[mt] = *(const float4*)&As[r * GSTR + kp * 16 + 4 * tg];
                aB[mt] = *(const float4*)&As[(r + 8) * GSTR + kp * 16 + 4 * tg];
            }
            #pragma unroll
            for (int nt = 0; nt < 4; nt++) {
                int n = wn * 32 + nt * 8 + g;
                float4 b4 = *(const float4*)&Bs[n * GSTR + kp * 16 + 4 * tg];
                #pragma unroll
                for (int mt = 0; mt < 4; mt++) {
                    mma8(acc[mt][nt], fb(aA[mt].x), fb(aB[mt].x),
                                      fb(aA[mt].y), fb(aB[mt].y),
                                      fb(b4.x), fb(b4.y));
                    mma8(acc[mt][nt], fb(aA[mt].z), fb(aB[mt].z),
                                      fb(aA[mt].w), fb(aB[mt].w),
                                      fb(b4.z), fb(b4.w));
                }
            }
        }
    }
    __syncthreads();

    // Epilogue: bias + tf32 round + scatter with pos16/perm8 permutations.
    #pragma unroll
    for (int mt = 0; mt < 4; mt++) {
        int r = m0 + wm * 64 + mt * 16 + g;
        int b_  = r >> 11, s_ = r & 2047;
        int b8_ = (r + 8) >> 11, s8_ = (r + 8) & 2047;
        float em0 = 1.f, em8 = 1.f;
        if (vtrans) {
            em0 = exp2f(mask[b_  * SS + s_ ] * LOG2E);
            em8 = exp2f(mask[b8_ * SS + s8_] * LOG2E);
        }
        #pragma unroll
        for (int nt = 0; nt < 4; nt++) {
            int c = n0 + wn * 32 + nt * 8 + 2 * tg;
            int nh = (c >> 6) & 15, hd = c & 63;
            float bi0 = bias[c], bi1 = bias[c + 1];
            int h0 = (b_  << 4) + nh;
            int h8 = (b8_ << 4) + nh;
            if (vtrans) {
                float v0 = tf32r((acc[mt][nt][0] + bi0) * em0);
                float v1 = tf32r((acc[mt][nt][1] + bi1) * em0);
                float v2 = tf32r((acc[mt][nt][2] + bi0) * em8);
                float v3 = tf32r((acc[mt][nt][3] + bi1) * em8);
                int sp0 = (s_  & ~15) | pos16(s_  & 15);
                int sp8 = (s8_ & ~15) | pos16(s8_ & 15);
                int t0 = (h0 * HDD + hd) * SS + sp0;
                int t8 = (h8 * HDD + hd) * SS + sp8;
                out[t0]      = v0;
                out[t0 + SS] = v1;
                out[t8]      = v2;
                out[t8 + SS] = v3;
            } else {
                float v0 = tf32r((acc[mt][nt][0] + bi0) * oscale);
                float v1 = tf32r((acc[mt][nt][1] + bi1) * oscale);
                float v2 = tf32r((acc[mt][nt][2] + bi0) * oscale);
                float v3 = tf32r((acc[mt][nt][3] + bi1) * oscale);
                int l = hd & 15;
                int p0 = (hd & ~15) | pos16(l);
                int p1 = (hd & ~15) | pos16(l + 1);
                int so_ = s_, so8 = s8_;
                if (kperm) {
                    so_ = (s_  & ~7) | perm8(s_  & 7);
                    so8 = (s8_ & ~7) | perm8(s8_ & 7);
                }
                int base0 = (h0 * SS + so_) * HDD;
                int base8 = (h8 * SS + so8) * HDD;
                out[base0 + p0] = v0;
                out[base0 + p1] = v1;
                out[base8 + p0] = v2;
                out[base8 + p1] = v3;
            }
        }
    }
}

// ======================= Flash attention =======================
// 8 warps, 128 q-rows, 2 CTA/SM. Mask folded into V -> p = exp2(s).
// l computed SCALAR on the FMA pipe: l += p*em with em from a perm8-indexed
// smem table (unbundles R15's tensor-core l-column; PV back to 8 n-groups).
#define KSTR 80
#define TILE_F (64 * KSTR)
#define ATTN_SMEM ((4 * TILE_F + SS) * (int)sizeof(float))

__global__ __launch_bounds__(256, 2) void attn_kernel(const float* __restrict__ mask,
                                                      float* __restrict__ out)
{
    extern __shared__ float sm[];
    float* Em = sm + 4 * TILE_F;           // em[2048], perm8-permuted (S key order)

    const int tid = threadIdx.x;
    const int lane = tid & 31, warp = tid >> 5;
    const int g = lane >> 2, tg = lane & 3;
    const int hbh = blockIdx.y;
    const int b = hbh >> 4, nh = hbh & 15;
    const int q0 = blockIdx.x * 128;
    const int r0 = warp * 16;

    const float* qb  = g_q + ((size_t)hbh * SS + q0) * HDD;
    const float* kb  = g_k + (size_t)hbh * SS * HDD;
    const float* vtb = g_v + (size_t)hbh * HDD * SS;
    const float* mrow = mask + b * SS;

    // em table, perm8 within 8 to match S accumulator key order
    #pragma unroll
    for (int i = 0; i < 8; i++) {
        int idx = tid + i * 256;
        Em[(idx & ~7) | perm8(idx & 7)] = exp2f(mrow[idx] * LOG2E);
    }

    // Q fragments: hd pos16'd -> one LDG.128 covers both k8-groups of a pair
    uint32_t qa[4][8];
    #pragma unroll
    for (int kp = 0; kp < 4; kp++) {
        float4 qA = *(const float4*)&qb[(r0 + g)     * 64 + kp * 16 + 4 * tg];
        float4 qB = *(const float4*)&qb[(r0 + 8 + g) * 64 + kp * 16 + 4 * tg];
        qa[kp][0] = fb(qA.x); qa[kp][1] = fb(qB.x);
        qa[kp][2] = fb(qA.y); qa[kp][3] = fb(qB.y);
        qa[kp][4] = fb(qA.z); qa[kp][5] = fb(qB.z);
        qa[kp][6] = fb(qA.w); qa[kp][7] = fb(qB.w);
    }

    const uint32_t smem_base = (uint32_t)__cvta_generic_to_shared(sm);

    float O[8][4];
    #pragma unroll
    for (int nt = 0; nt < 8; nt++)
        #pragma unroll
        for (int j = 0; j < 4; j++) O[nt][j] = 0.f;
    float lA = 0.f, lB = 0.f;

    {
        #pragma unroll
        for (int i = 0; i < 4; i++) {
            int c = tid + i * 256;
            int row = c >> 4, c4 = (c & 15) * 4;
            cpasync16(smem_base + (row * KSTR + c4) * 4, &kb[row * 64 + c4]);
            cpasync16(smem_base + (2 * TILE_F + row * KSTR + c4) * 4,
                      &vtb[(size_t)row * SS + c4]);
        }
        cpcommit();
    }

    for (int kt = 0; kt < 32; kt++) {
        const int cur = kt & 1;
        float* Ks = sm + cur * TILE_F;
        float* Vt = sm + 2 * TILE_F + cur * TILE_F;

        cpwait0();
        __syncthreads();

        if (kt + 1 < 32) {
            const int nxt = (kt + 1) & 1;
            const int koff = (kt + 1) * 64;
            #pragma unroll
            for (int i = 0; i < 4; i++) {
                int c = tid + i * 256;
                int row = c >> 4, c4 = (c & 15) * 4;
                cpasync16(smem_base + (nxt * TILE_F + row * KSTR + c4) * 4,
                          &kb[(koff + row) * 64 + c4]);
                cpasync16(smem_base + ((2 + nxt) * TILE_F + row * KSTR + c4) * 4,
                          &vtb[(size_t)row * SS + koff + c4]);
            }
            cpcommit();
        }

        // S = Q K^T (log2 domain, mask-free)
        float s[8][4];
        #pragma unroll
        for (int kg = 0; kg < 8; kg++)
            #pragma unroll
            for (int j = 0; j < 4; j++) s[kg][j] = 0.f;

        #pragma unroll
        for (int kp = 0; kp < 4; kp++) {
            #pragma unroll
            for (int kg = 0; kg < 8; kg++) {
                float4 kk = *(const float4*)&Ks[(kg * 8 + g) * KSTR + kp * 16 + 4 * tg];
                mma8(s[kg], qa[kp][0], qa[kp][1], qa[kp][2], qa[kp][3],
                     fb(kk.x), fb(kk.y));
                mma8(s[kg], qa[kp][4], qa[kp][5], qa[kp][6], qa[kp][7],
                     fb(kk.z), fb(kk.w));
            }
        }

        // exp2 per element; l accumulated scalar on FMA pipe (p*em); then PV.
        const float* Et = Em + kt * 64;
        #pragma unroll
        for (int kp = 0; kp < 4; kp++) {
            #pragma unroll
            for (int h = 0; h < 2; h++) {
                int kg = 2 * kp + h;
                float2 em = *(const float2*)&Et[kg * 8 + 2 * tg];
                float p0 = exp2f(s[kg][0]);
                float p1 = exp2f(s[kg][1]);
                float p2 = exp2f(s[kg][2]);
                float p3 = exp2f(s[kg][3]);
                lA = fmaf(p0, em.x, fmaf(p1, em.y, lA));
                lB = fmaf(p2, em.x, fmaf(p3, em.y, lB));
                s[kg][0] = p0; s[kg][1] = p1;
                s[kg][2] = p2; s[kg][3] = p3;
            }
            #pragma unroll
            for (int nt = 0; nt < 8; nt++) {
                float4 vv = *(const float4*)&Vt[(nt * 8 + g) * KSTR + kp * 16 + 4 * tg];
                mma8(O[nt], fb(s[2 * kp][0]), fb(s[2 * kp][2]),
                            fb(s[2 * kp][1]), fb(s[2 * kp][3]),
                     fb(vv.x), fb(vv.y));
                mma8(O[nt], fb(s[2 * kp + 1][0]), fb(s[2 * kp + 1][2]),
                            fb(s[2 * kp + 1][1]), fb(s[2 * kp + 1][3]),
                     fb(vv.z), fb(vv.w));
            }
        }
    }

    // Final l-reduce across the 4 tg lanes of each row
    lA += __shfl_xor_sync(0xffffffffu, lA, 1);
    lA += __shfl_xor_sync(0xffffffffu, lA, 2);
    lB += __shfl_xor_sync(0xffffffffu, lB, 1);
    lB += __shfl_xor_sync(0xffffffffu, lB, 2);

    float i0 = 1.f / lA, i1 = 1.f / lB;
    int rg  = q0 + r0 + g;
    int rg8 = rg + 8;
    #pragma unroll
    for (int nt = 0; nt < 8; nt++) {
        int hd = nt * 8 + 2 * tg;
        int o0 = (b * SS + rg ) * HH + nh * 64 + hd;
        int o8 = (b * SS + rg8) * HH + nh * 64 + hd;
        out[o0]     = O[nt][0] * i0;
        out[o0 + 1] = O[nt][1] * i0;
        out[o8]     = O[nt][2] * i1;
        out[o8 + 1] = O[nt][3] * i1;
    }
}

extern "C" void kernel_launch(void* const* d_in, const int* in_sizes, int n_in,
                              void* d_out, int out_size)
{
    const float* X    = (const float*)d_in[0];
    const float* mask = (const float*)d_in[1];
    const float* Wq   = (const float*)d_in[2];
    const float* bq   = (const float*)d_in[3];
    const float* Wk   = (const float*)d_in[4];
    const float* bk   = (const float*)d_in[5];
    const float* Wv   = (const float*)d_in[6];
    const float* bv   = (const float*)d_in[7];
    float* out = (float*)d_out;

    cudaFuncSetAttribute(qkv_gemm_kernel, cudaFuncAttributeMaxDynamicSharedMemorySize, GEMM_SMEM);
    cudaFuncSetAttribute(attn_kernel, cudaFuncAttributeMaxDynamicSharedMemorySize, ATTN_SMEM);

    int total_groups = XGRP16 + 3 * WGRP16;
    preround_kernel<<<total_groups / 256, 256>>>(X, Wq, Wk, Wv);

    dim3 gg(8192 / 128, HH / 128, 3);
    qkv_gemm_kernel<<<gg, 256, GEMM_SMEM>>>(bq, bk, bv, mask);

    dim3 ga(SS / 128, BH);
    attn_kernel<<<ga, 256, ATTN_SMEM>>>(mask, out);
}